// round 1
// baseline (speedup 1.0000x reference)
#include <cuda_runtime.h>

// Chamfer distance, B=8, Np=Ng=8192, D=3.
// One fused pass computes both min directions; scratch in __device__ globals.

#define BB 8
#define NN 8192
#define THREADS 256
#define RR 8
#define TILE_P (THREADS * RR)      // 2048 pred points per block
#define PBLK (NN / TILE_P)         // 4
#define SPLIT_G 16
#define CHUNK_G (NN / SPLIT_G)     // 512 gt points per block

// Global scratch: per-point running mins as order-preserving uints.
__device__ unsigned g_minp[BB * NN];
__device__ unsigned g_ming[BB * NN];

// Monotone float<->uint mapping (handles negatives from fp cancellation).
__device__ __forceinline__ unsigned f2o(float f) {
    unsigned b = __float_as_uint(f);
    return (b & 0x80000000u) ? ~b : (b | 0x80000000u);
}
__device__ __forceinline__ float o2f(unsigned o) {
    return __uint_as_float((o & 0x80000000u) ? (o ^ 0x80000000u) : ~o);
}

#define ORD_INF 0xFF800000u  // f2o(+inf)

__global__ void chamfer_init() {
    int i = blockIdx.x * blockDim.x + threadIdx.x;
    if (i < BB * NN) {
        g_minp[i] = ORD_INF;
        g_ming[i] = ORD_INF;
    }
}

__global__ __launch_bounds__(THREADS)
void chamfer_main(const float* __restrict__ pred, const float* __restrict__ gt) {
    const int bs = blockIdx.x;          // [0, BB*PBLK)
    const int b  = bs / PBLK;
    const int pb = bs % PBLK;
    const int gs = blockIdx.y;          // [0, SPLIT_G)
    const int tid = threadIdx.x;
    const int lane = tid & 31;

    __shared__ float4   shg[CHUNK_G];   // (-2x, -2y, -2z, x^2+y^2+z^2)
    __shared__ unsigned shmin[CHUNK_G]; // per-gt block-local min (ordered uint)

    // Stage gt chunk into shared.
    const float* gtb = gt + ((long)b * NN + (long)gs * CHUNK_G) * 3;
    for (int j = tid; j < CHUNK_G; j += THREADS) {
        float x = gtb[j * 3 + 0];
        float y = gtb[j * 3 + 1];
        float z = gtb[j * 3 + 2];
        shg[j] = make_float4(-2.0f * x, -2.0f * y, -2.0f * z,
                             x * x + y * y + z * z);
        shmin[j] = ORD_INF;
    }

    // Load R pred points per thread into registers.
    float px[RR], py[RR], pz[RR], p2[RR], mp[RR];
    const float* pbase = pred + ((long)b * NN + (long)pb * TILE_P) * 3;
#pragma unroll
    for (int r = 0; r < RR; r++) {
        int i = r * THREADS + tid;
        float x = pbase[i * 3 + 0];
        float y = pbase[i * 3 + 1];
        float z = pbase[i * 3 + 2];
        px[r] = x; py[r] = y; pz[r] = z;
        p2[r] = x * x + y * y + z * z;
        mp[r] = __int_as_float(0x7F800000);  // +inf
    }
    __syncthreads();

    // Main loop over gt chunk.
#pragma unroll 2
    for (int j = 0; j < CHUNK_G; j++) {
        float4 g = shg[j];
        float t[RR];
#pragma unroll
        for (int r = 0; r < RR; r++) {
            float a = p2[r] + g.w;          // p^2 + g^2
            a = fmaf(g.x, px[r], a);        // -2 p.g accumulated
            a = fmaf(g.y, py[r], a);
            a = fmaf(g.z, pz[r], a);
            t[r] = a;
            mp[r] = fminf(mp[r], a);        // pred -> gt direction
        }
        // gt -> pred direction: tree min over R, then warp min.
        float m01 = fminf(t[0], t[1]);
        float m23 = fminf(t[2], t[3]);
        float m45 = fminf(t[4], t[5]);
        float m67 = fminf(t[6], t[7]);
        float m = fminf(fminf(m01, m23), fminf(m45, m67));
#pragma unroll
        for (int off = 16; off > 0; off >>= 1)
            m = fminf(m, __shfl_xor_sync(0xFFFFFFFFu, m, off));
        if (lane == 0)
            atomicMin(&shmin[j], f2o(m));
    }
    __syncthreads();

    // Publish gt-direction mins.
    unsigned* gm = g_ming + (long)b * NN + (long)gs * CHUNK_G;
    for (int j = tid; j < CHUNK_G; j += THREADS)
        atomicMin(&gm[j], shmin[j]);

    // Publish pred-direction mins.
    unsigned* pm = g_minp + (long)b * NN + (long)pb * TILE_P;
#pragma unroll
    for (int r = 0; r < RR; r++)
        atomicMin(&pm[r * THREADS + tid], f2o(mp[r]));
}

__global__ void chamfer_finalize(float* __restrict__ out) {
    __shared__ double sh[THREADS];
    double local = 0.0;
    for (int i = threadIdx.x; i < BB * NN; i += THREADS)
        local += (double)o2f(g_minp[i]) + (double)o2f(g_ming[i]);
    sh[threadIdx.x] = local;
    __syncthreads();
    for (int s = THREADS / 2; s > 0; s >>= 1) {
        if (threadIdx.x < s) sh[threadIdx.x] += sh[threadIdx.x + s];
        __syncthreads();
    }
    if (threadIdx.x == 0)
        out[0] = (float)(sh[0] / ((double)NN * (double)BB));
}

extern "C" void kernel_launch(void* const* d_in, const int* in_sizes, int n_in,
                              void* d_out, int out_size) {
    const float* pred = (const float*)d_in[0];
    const float* gt   = (const float*)d_in[1];
    float* out = (float*)d_out;

    chamfer_init<<<(BB * NN + 255) / 256, 256>>>();
    dim3 grid(BB * PBLK, SPLIT_G);
    chamfer_main<<<grid, THREADS>>>(pred, gt);
    chamfer_finalize<<<1, THREADS>>>(out);
}

// round 2
// speedup vs baseline: 1.1814x; 1.1814x over previous
#include <cuda_runtime.h>

// Chamfer distance, B=8, Np=Ng=8192, D=3.
// Fused single pass over all pairs; packed f32x2 FMA inner loop.

#define BB 8
#define NN 8192
#define THREADS 256
#define RR 8                        // pred points per thread (4 packed pairs)
#define RP (RR / 2)
#define TILE_P (THREADS * RR)       // 2048 pred points per block
#define PBLK (NN / TILE_P)          // 4
#define SPLIT_G 16
#define CHUNK_G (NN / SPLIT_G)      // 512 gt points per block

__device__ unsigned g_minp[BB * NN];
__device__ unsigned g_ming[BB * NN];

// Monotone float<->uint map (values can be slightly negative from cancellation).
__device__ __forceinline__ unsigned f2o(float f) {
    unsigned b = __float_as_uint(f);
    return (b & 0x80000000u) ? ~b : (b | 0x80000000u);
}
__device__ __forceinline__ float o2f(unsigned o) {
    return __uint_as_float((o & 0x80000000u) ? (o ^ 0x80000000u) : ~o);
}
#define ORD_INF 0xFF800000u  // f2o(+inf)

// ---- packed f32x2 helpers (Blackwell; ptxas won't auto-fuse) ----
__device__ __forceinline__ unsigned long long add2(unsigned long long a, unsigned long long b) {
    unsigned long long d;
    asm("add.rn.f32x2 %0, %1, %2;" : "=l"(d) : "l"(a), "l"(b));
    return d;
}
__device__ __forceinline__ unsigned long long fma2(unsigned long long a, unsigned long long b,
                                                   unsigned long long c) {
    unsigned long long d;
    asm("fma.rn.f32x2 %0, %1, %2, %3;" : "=l"(d) : "l"(a), "l"(b), "l"(c));
    return d;
}
__device__ __forceinline__ unsigned long long pack2(float lo, float hi) {
    unsigned long long d;
    asm("mov.b64 %0, {%1, %2};" : "=l"(d) : "f"(lo), "f"(hi));
    return d;
}
__device__ __forceinline__ void unpack2(float& lo, float& hi, unsigned long long a) {
    asm("mov.b64 {%0, %1}, %2;" : "=f"(lo), "=f"(hi) : "l"(a));
}

__global__ void chamfer_init() {
    int i = blockIdx.x * blockDim.x + threadIdx.x;
    if (i < BB * NN) {
        g_minp[i] = ORD_INF;
        g_ming[i] = ORD_INF;
    }
}

__global__ __launch_bounds__(THREADS, 3)
void chamfer_main(const float* __restrict__ pred, const float* __restrict__ gt) {
    const int bs = blockIdx.x;          // [0, BB*PBLK)
    const int b  = bs / PBLK;
    const int pb = bs % PBLK;
    const int gs = blockIdx.y;          // [0, SPLIT_G)
    const int tid = threadIdx.x;
    const int lane = tid & 31;

    // Duplicated-lane packed gt data: shga[j]={-2x,-2x,-2y,-2y}, shgb[j]={-2z,-2z,g2,g2}
    __shared__ float4   shga[CHUNK_G];
    __shared__ float4   shgb[CHUNK_G];
    __shared__ unsigned shmin[CHUNK_G];

    const float* gtb = gt + ((long)b * NN + (long)gs * CHUNK_G) * 3;
    for (int j = tid; j < CHUNK_G; j += THREADS) {
        float x = gtb[j * 3 + 0];
        float y = gtb[j * 3 + 1];
        float z = gtb[j * 3 + 2];
        float nx = -2.0f * x, ny = -2.0f * y, nz = -2.0f * z;
        float w = x * x + y * y + z * z;
        shga[j] = make_float4(nx, nx, ny, ny);
        shgb[j] = make_float4(nz, nz, w, w);
        shmin[j] = ORD_INF;
    }

    // RR pred points per thread, packed in pairs.
    unsigned long long px2[RP], py2[RP], pz2[RP], pw2[RP];
    float mp[RR];
    const float* pbase = pred + ((long)b * NN + (long)pb * TILE_P) * 3;
#pragma unroll
    for (int p = 0; p < RP; p++) {
        int i0 = (2 * p) * THREADS + tid;
        int i1 = (2 * p + 1) * THREADS + tid;
        float x0 = pbase[i0 * 3 + 0], y0 = pbase[i0 * 3 + 1], z0 = pbase[i0 * 3 + 2];
        float x1 = pbase[i1 * 3 + 0], y1 = pbase[i1 * 3 + 1], z1 = pbase[i1 * 3 + 2];
        px2[p] = pack2(x0, x1);
        py2[p] = pack2(y0, y1);
        pz2[p] = pack2(z0, z1);
        pw2[p] = pack2(x0 * x0 + y0 * y0 + z0 * z0,
                       x1 * x1 + y1 * y1 + z1 * z1);
        mp[2 * p]     = __int_as_float(0x7F800000);
        mp[2 * p + 1] = __int_as_float(0x7F800000);
    }
    __syncthreads();

    const ulonglong2* ga = reinterpret_cast<const ulonglong2*>(shga);
    const ulonglong2* gb = reinterpret_cast<const ulonglong2*>(shgb);

    // Main loop, unrolled by 2 so the two warp-reduce chains interleave.
    for (int j = 0; j < CHUNK_G; j += 2) {
        ulonglong2 A0 = ga[j],     B0 = gb[j];
        ulonglong2 A1 = ga[j + 1], B1 = gb[j + 1];

        float m0, m1;
        {
            float tm[RP];
#pragma unroll
            for (int p = 0; p < RP; p++) {
                unsigned long long a = add2(pw2[p], B0.y);
                a = fma2(A0.x, px2[p], a);
                a = fma2(A0.y, py2[p], a);
                a = fma2(B0.x, pz2[p], a);
                float lo, hi;
                unpack2(lo, hi, a);
                mp[2 * p]     = fminf(mp[2 * p], lo);
                mp[2 * p + 1] = fminf(mp[2 * p + 1], hi);
                tm[p] = fminf(lo, hi);
            }
            m0 = fminf(fminf(tm[0], tm[1]), fminf(tm[2], tm[3]));
        }
        {
            float tm[RP];
#pragma unroll
            for (int p = 0; p < RP; p++) {
                unsigned long long a = add2(pw2[p], B1.y);
                a = fma2(A1.x, px2[p], a);
                a = fma2(A1.y, py2[p], a);
                a = fma2(B1.x, pz2[p], a);
                float lo, hi;
                unpack2(lo, hi, a);
                mp[2 * p]     = fminf(mp[2 * p], lo);
                mp[2 * p + 1] = fminf(mp[2 * p + 1], hi);
                tm[p] = fminf(lo, hi);
            }
            m1 = fminf(fminf(tm[0], tm[1]), fminf(tm[2], tm[3]));
        }
        // Interleaved butterfly reductions (two independent chains).
#pragma unroll
        for (int off = 16; off > 0; off >>= 1) {
            m0 = fminf(m0, __shfl_xor_sync(0xFFFFFFFFu, m0, off));
            m1 = fminf(m1, __shfl_xor_sync(0xFFFFFFFFu, m1, off));
        }
        if (lane == 0) {
            atomicMin(&shmin[j],     f2o(m0));
            atomicMin(&shmin[j + 1], f2o(m1));
        }
    }
    __syncthreads();

    unsigned* gm = g_ming + (long)b * NN + (long)gs * CHUNK_G;
    for (int j = tid; j < CHUNK_G; j += THREADS)
        atomicMin(&gm[j], shmin[j]);

    unsigned* pm = g_minp + (long)b * NN + (long)pb * TILE_P;
#pragma unroll
    for (int r = 0; r < RR; r++)
        atomicMin(&pm[r * THREADS + tid], f2o(mp[r]));
}

#define FTHREADS 1024
__global__ __launch_bounds__(FTHREADS)
void chamfer_finalize(float* __restrict__ out) {
    __shared__ double sh[FTHREADS];
    double a0 = 0.0, a1 = 0.0, a2 = 0.0, a3 = 0.0;
    const int total = BB * NN;
    for (int i = threadIdx.x; i < total; i += 4 * FTHREADS) {
        a0 += (double)o2f(g_minp[i]) + (double)o2f(g_ming[i]);
        int i1 = i + FTHREADS;
        int i2 = i + 2 * FTHREADS;
        int i3 = i + 3 * FTHREADS;
        if (i1 < total) a1 += (double)o2f(g_minp[i1]) + (double)o2f(g_ming[i1]);
        if (i2 < total) a2 += (double)o2f(g_minp[i2]) + (double)o2f(g_ming[i2]);
        if (i3 < total) a3 += (double)o2f(g_minp[i3]) + (double)o2f(g_ming[i3]);
    }
    sh[threadIdx.x] = (a0 + a1) + (a2 + a3);
    __syncthreads();
    for (int s = FTHREADS / 2; s > 0; s >>= 1) {
        if (threadIdx.x < s) sh[threadIdx.x] += sh[threadIdx.x + s];
        __syncthreads();
    }
    if (threadIdx.x == 0)
        out[0] = (float)(sh[0] / ((double)NN * (double)BB));
}

extern "C" void kernel_launch(void* const* d_in, const int* in_sizes, int n_in,
                              void* d_out, int out_size) {
    const float* pred = (const float*)d_in[0];
    const float* gt   = (const float*)d_in[1];
    float* out = (float*)d_out;

    chamfer_init<<<(BB * NN + 255) / 256, 256>>>();
    dim3 grid(BB * PBLK, SPLIT_G);
    chamfer_main<<<grid, THREADS>>>(pred, gt);
    chamfer_finalize<<<1, FTHREADS>>>(out);
}

// round 4
// speedup vs baseline: 2.1004x; 1.7779x over previous
#include <cuda_runtime.h>

// Chamfer distance, B=8, Np=Ng=8192, D=3.
// Fused pass; f32x2 packed FMAs; redux.sync.min.u32 on ordered-uint keys;
// no atomics; single-wave launch (occ 4, 512 blocks <= 592 slots).

#define BB 8
#define NN 8192
#define THREADS 256
#define RR 8                        // pred points per thread (4 packed pairs)
#define RP (RR / 2)
#define TILE_P (THREADS * RR)       // 2048 pred points per block
#define PBLK (NN / TILE_P)          // 4
#define SPLIT_G 16
#define CHUNK_G (NN / SPLIT_G)      // 512 gt points per block
#define NWARP (THREADS / 32)

// Privatized partial minima (plain stores; every slot written, no init).
__device__ float g_minp_part[SPLIT_G][BB * NN];
__device__ float g_ming_part[PBLK][BB * NN];
__device__ double g_partial[128];

// Monotone float<->uint map (distances can be slightly negative from cancellation).
__device__ __forceinline__ unsigned f2o(float f) {
    unsigned b = __float_as_uint(f);
    return b ^ (unsigned)(((int)b >> 31) | 0x80000000);
}
__device__ __forceinline__ float o2f(unsigned o) {
    return __uint_as_float(o ^ (unsigned)((~(int)o >> 31) | 0x80000000));
}

// ---- packed f32x2 helpers ----
__device__ __forceinline__ unsigned long long add2(unsigned long long a, unsigned long long b) {
    unsigned long long d;
    asm("add.rn.f32x2 %0, %1, %2;" : "=l"(d) : "l"(a), "l"(b));
    return d;
}
__device__ __forceinline__ unsigned long long fma2(unsigned long long a, unsigned long long b,
                                                   unsigned long long c) {
    unsigned long long d;
    asm("fma.rn.f32x2 %0, %1, %2, %3;" : "=l"(d) : "l"(a), "l"(b), "l"(c));
    return d;
}
__device__ __forceinline__ unsigned long long pack2(float lo, float hi) {
    unsigned long long d;
    asm("mov.b64 %0, {%1, %2};" : "=l"(d) : "f"(lo), "f"(hi));
    return d;
}
__device__ __forceinline__ void unpack2(float& lo, float& hi, unsigned long long a) {
    asm("mov.b64 {%0, %1}, %2;" : "=f"(lo), "=f"(hi) : "l"(a));
}
// Warp-wide u32 min in one instruction (sm_80+).
__device__ __forceinline__ unsigned redux_min_u32(unsigned v) {
    unsigned d;
    asm("redux.sync.min.u32 %0, %1, %2;" : "=r"(d) : "r"(v), "r"(0xFFFFFFFFu));
    return d;
}

__global__ __launch_bounds__(THREADS, 4)
void chamfer_main(const float* __restrict__ pred, const float* __restrict__ gt) {
    const int bs = blockIdx.x;          // [0, BB*PBLK)
    const int b  = bs / PBLK;
    const int pb = bs % PBLK;
    const int gs = blockIdx.y;          // [0, SPLIT_G)
    const int tid = threadIdx.x;
    const int lane = tid & 31;
    const int warp = tid >> 5;

    // Duplicated-lane packed gt: shga[j]={-2x,-2x,-2y,-2y}, shgb[j]={-2z,-2z,g2,g2}
    __shared__ float4   shga[CHUNK_G];
    __shared__ float4   shgb[CHUNK_G];
    __shared__ unsigned shminw[NWARP][CHUNK_G];   // per-warp min, ordered-uint

    const float* gtb = gt + ((long)b * NN + (long)gs * CHUNK_G) * 3;
    for (int j = tid; j < CHUNK_G; j += THREADS) {
        float x = gtb[j * 3 + 0];
        float y = gtb[j * 3 + 1];
        float z = gtb[j * 3 + 2];
        float nx = -2.0f * x, ny = -2.0f * y, nz = -2.0f * z;
        float w = x * x + y * y + z * z;
        shga[j] = make_float4(nx, nx, ny, ny);
        shgb[j] = make_float4(nz, nz, w, w);
    }

    // RR pred points per thread, packed in pairs.
    unsigned long long px2[RP], py2[RP], pz2[RP], pw2[RP];
    float mp[RR];
    const float* pbase = pred + ((long)b * NN + (long)pb * TILE_P) * 3;
#pragma unroll
    for (int p = 0; p < RP; p++) {
        int i0 = (2 * p) * THREADS + tid;
        int i1 = (2 * p + 1) * THREADS + tid;
        float x0 = pbase[i0 * 3 + 0], y0 = pbase[i0 * 3 + 1], z0 = pbase[i0 * 3 + 2];
        float x1 = pbase[i1 * 3 + 0], y1 = pbase[i1 * 3 + 1], z1 = pbase[i1 * 3 + 2];
        px2[p] = pack2(x0, x1);
        py2[p] = pack2(y0, y1);
        pz2[p] = pack2(z0, z1);
        pw2[p] = pack2(x0 * x0 + y0 * y0 + z0 * z0,
                       x1 * x1 + y1 * y1 + z1 * z1);
        mp[2 * p]     = __int_as_float(0x7F800000);
        mp[2 * p + 1] = __int_as_float(0x7F800000);
    }
    __syncthreads();

    const ulonglong2* ga = reinterpret_cast<const ulonglong2*>(shga);
    const ulonglong2* gb = reinterpret_cast<const ulonglong2*>(shgb);

    for (int j = 0; j < CHUNK_G; j += 2) {
        ulonglong2 A0 = ga[j],     B0 = gb[j];
        ulonglong2 A1 = ga[j + 1], B1 = gb[j + 1];

        float m0, m1;
        {
            float tm[RP];
#pragma unroll
            for (int p = 0; p < RP; p++) {
                unsigned long long a = add2(pw2[p], B0.y);
                a = fma2(A0.x, px2[p], a);
                a = fma2(A0.y, py2[p], a);
                a = fma2(B0.x, pz2[p], a);
                float lo, hi;
                unpack2(lo, hi, a);
                mp[2 * p]     = fminf(mp[2 * p], lo);
                mp[2 * p + 1] = fminf(mp[2 * p + 1], hi);
                tm[p] = fminf(lo, hi);
            }
            m0 = fminf(fminf(tm[0], tm[1]), fminf(tm[2], tm[3]));
        }
        {
            float tm[RP];
#pragma unroll
            for (int p = 0; p < RP; p++) {
                unsigned long long a = add2(pw2[p], B1.y);
                a = fma2(A1.x, px2[p], a);
                a = fma2(A1.y, py2[p], a);
                a = fma2(B1.x, pz2[p], a);
                float lo, hi;
                unpack2(lo, hi, a);
                mp[2 * p]     = fminf(mp[2 * p], lo);
                mp[2 * p + 1] = fminf(mp[2 * p + 1], hi);
                tm[p] = fminf(lo, hi);
            }
            m1 = fminf(fminf(tm[0], tm[1]), fminf(tm[2], tm[3]));
        }
        // Integer-domain warp min; two independent 1-instruction reductions.
        unsigned u0 = redux_min_u32(f2o(m0));
        unsigned u1 = redux_min_u32(f2o(m1));
        if (lane == 0) {
            shminw[warp][j]     = u0;
            shminw[warp][j + 1] = u1;
        }
    }
    __syncthreads();

    // gt-direction publish: combine 8 warps (integer min), decode, plain store.
    float* gm = g_ming_part[pb] + (long)b * NN + (long)gs * CHUNK_G;
    for (int j = tid; j < CHUNK_G; j += THREADS) {
        unsigned v = shminw[0][j];
#pragma unroll
        for (int w = 1; w < NWARP; w++) v = min(v, shminw[w][j]);
        gm[j] = o2f(v);
    }

    // pred-direction publish: plain store to this gs's slice.
    float* pm = g_minp_part[gs] + (long)b * NN + (long)pb * TILE_P;
#pragma unroll
    for (int r = 0; r < RR; r++)
        pm[r * THREADS + tid] = mp[r];
}

#define F1BLOCKS 128
#define F1T 256
#define PTS_PER_BLK (BB * NN / F1BLOCKS)   // 512

__global__ __launch_bounds__(F1T)
void chamfer_finalize1() {
    __shared__ double sh[F1T];
    const int base = blockIdx.x * PTS_PER_BLK;
    double acc = 0.0;
    for (int i = threadIdx.x; i < PTS_PER_BLK; i += F1T) {
        int idx = base + i;
        float vp = g_minp_part[0][idx];
#pragma unroll
        for (int s = 1; s < SPLIT_G; s++) vp = fminf(vp, g_minp_part[s][idx]);
        float vg = g_ming_part[0][idx];
#pragma unroll
        for (int s = 1; s < PBLK; s++) vg = fminf(vg, g_ming_part[s][idx]);
        acc += (double)vp + (double)vg;
    }
    sh[threadIdx.x] = acc;
    __syncthreads();
    for (int s = F1T / 2; s > 0; s >>= 1) {
        if (threadIdx.x < s) sh[threadIdx.x] += sh[threadIdx.x + s];
        __syncthreads();
    }
    if (threadIdx.x == 0) g_partial[blockIdx.x] = sh[0];
}

__global__ void chamfer_finalize2(float* __restrict__ out) {
    __shared__ double sh[F1BLOCKS];
    sh[threadIdx.x] = g_partial[threadIdx.x];
    __syncthreads();
    for (int s = F1BLOCKS / 2; s > 0; s >>= 1) {
        if (threadIdx.x < s) sh[threadIdx.x] += sh[threadIdx.x + s];
        __syncthreads();
    }
    if (threadIdx.x == 0)
        out[0] = (float)(sh[0] / ((double)NN * (double)BB));
}

extern "C" void kernel_launch(void* const* d_in, const int* in_sizes, int n_in,
                              void* d_out, int out_size) {
    const float* pred = (const float*)d_in[0];
    const float* gt   = (const float*)d_in[1];
    float* out = (float*)d_out;

    dim3 grid(BB * PBLK, SPLIT_G);
    chamfer_main<<<grid, THREADS>>>(pred, gt);
    chamfer_finalize1<<<F1BLOCKS, F1T>>>();
    chamfer_finalize2<<<1, F1BLOCKS>>>(out);
}

// round 5
// speedup vs baseline: 2.3429x; 1.1154x over previous
#include <cuda_runtime.h>

// Chamfer distance, B=8, Np=Ng=8192, D=3.
// Fused pass; f32x2 packed FMAs; redux.sync.min.u32; no atomics.
// 128-thread CTAs @ occ 8 -> 1024 blocks, near-perfect SM load balance.

#define BB 8
#define NN 8192
#define THREADS 128
#define RR 8                        // pred points per thread (4 packed pairs)
#define RP (RR / 2)
#define TILE_P (THREADS * RR)       // 1024 pred points per block
#define PBLK (NN / TILE_P)          // 8
#define SPLIT_G 16
#define CHUNK_G (NN / SPLIT_G)      // 512 gt points per block
#define NWARP (THREADS / 32)        // 4

// Privatized partial minima (plain stores; every slot written, no init).
__device__ float g_minp_part[SPLIT_G][BB * NN];
__device__ float g_ming_part[PBLK][BB * NN];
__device__ double g_partial[128];

// Monotone float<->uint map (distances can dip slightly negative).
__device__ __forceinline__ unsigned f2o(float f) {
    unsigned b = __float_as_uint(f);
    return b ^ (unsigned)(((int)b >> 31) | 0x80000000);
}
__device__ __forceinline__ float o2f(unsigned o) {
    return __uint_as_float(o ^ (unsigned)((~(int)o >> 31) | 0x80000000));
}

// ---- packed f32x2 helpers ----
__device__ __forceinline__ unsigned long long add2(unsigned long long a, unsigned long long b) {
    unsigned long long d;
    asm("add.rn.f32x2 %0, %1, %2;" : "=l"(d) : "l"(a), "l"(b));
    return d;
}
__device__ __forceinline__ unsigned long long fma2(unsigned long long a, unsigned long long b,
                                                   unsigned long long c) {
    unsigned long long d;
    asm("fma.rn.f32x2 %0, %1, %2, %3;" : "=l"(d) : "l"(a), "l"(b), "l"(c));
    return d;
}
__device__ __forceinline__ unsigned long long pack2(float lo, float hi) {
    unsigned long long d;
    asm("mov.b64 %0, {%1, %2};" : "=l"(d) : "f"(lo), "f"(hi));
    return d;
}
__device__ __forceinline__ void unpack2(float& lo, float& hi, unsigned long long a) {
    asm("mov.b64 {%0, %1}, %2;" : "=f"(lo), "=f"(hi) : "l"(a));
}
__device__ __forceinline__ unsigned redux_min_u32(unsigned v) {
    unsigned d;
    asm("redux.sync.min.u32 %0, %1, %2;" : "=r"(d) : "r"(v), "r"(0xFFFFFFFFu));
    return d;
}

__global__ __launch_bounds__(THREADS, 8)
void chamfer_main(const float* __restrict__ pred, const float* __restrict__ gt) {
    const int bs = blockIdx.x;          // [0, BB*PBLK)
    const int b  = bs / PBLK;
    const int pb = bs % PBLK;
    const int gs = blockIdx.y;          // [0, SPLIT_G)
    const int tid = threadIdx.x;
    const int lane = tid & 31;
    const int warp = tid >> 5;

    // Duplicated-lane packed gt: shga[j]={-2x,-2x,-2y,-2y}, shgb[j]={-2z,-2z,g2,g2}
    __shared__ float4   shga[CHUNK_G];
    __shared__ float4   shgb[CHUNK_G];
    __shared__ unsigned shminw[NWARP][CHUNK_G];   // per-warp min, ordered-uint

    const float* gtb = gt + ((long)b * NN + (long)gs * CHUNK_G) * 3;
    for (int j = tid; j < CHUNK_G; j += THREADS) {
        float x = gtb[j * 3 + 0];
        float y = gtb[j * 3 + 1];
        float z = gtb[j * 3 + 2];
        float nx = -2.0f * x, ny = -2.0f * y, nz = -2.0f * z;
        float w = x * x + y * y + z * z;
        shga[j] = make_float4(nx, nx, ny, ny);
        shgb[j] = make_float4(nz, nz, w, w);
    }

    // RR pred points per thread, packed in pairs.
    unsigned long long px2[RP], py2[RP], pz2[RP], pw2[RP];
    float mp[RR];
    const float* pbase = pred + ((long)b * NN + (long)pb * TILE_P) * 3;
#pragma unroll
    for (int p = 0; p < RP; p++) {
        int i0 = (2 * p) * THREADS + tid;
        int i1 = (2 * p + 1) * THREADS + tid;
        float x0 = pbase[i0 * 3 + 0], y0 = pbase[i0 * 3 + 1], z0 = pbase[i0 * 3 + 2];
        float x1 = pbase[i1 * 3 + 0], y1 = pbase[i1 * 3 + 1], z1 = pbase[i1 * 3 + 2];
        px2[p] = pack2(x0, x1);
        py2[p] = pack2(y0, y1);
        pz2[p] = pack2(z0, z1);
        pw2[p] = pack2(x0 * x0 + y0 * y0 + z0 * z0,
                       x1 * x1 + y1 * y1 + z1 * z1);
        mp[2 * p]     = __int_as_float(0x7F800000);
        mp[2 * p + 1] = __int_as_float(0x7F800000);
    }
    __syncthreads();

    const ulonglong2* ga = reinterpret_cast<const ulonglong2*>(shga);
    const ulonglong2* gb = reinterpret_cast<const ulonglong2*>(shgb);

    for (int j = 0; j < CHUNK_G; j += 2) {
        ulonglong2 A0 = ga[j],     B0 = gb[j];
        ulonglong2 A1 = ga[j + 1], B1 = gb[j + 1];

        float m0, m1;
        {
            float tm[RP];
#pragma unroll
            for (int p = 0; p < RP; p++) {
                unsigned long long a = add2(pw2[p], B0.y);
                a = fma2(A0.x, px2[p], a);
                a = fma2(A0.y, py2[p], a);
                a = fma2(B0.x, pz2[p], a);
                float lo, hi;
                unpack2(lo, hi, a);
                mp[2 * p]     = fminf(mp[2 * p], lo);
                mp[2 * p + 1] = fminf(mp[2 * p + 1], hi);
                tm[p] = fminf(lo, hi);
            }
            m0 = fminf(fminf(tm[0], tm[1]), fminf(tm[2], tm[3]));
        }
        {
            float tm[RP];
#pragma unroll
            for (int p = 0; p < RP; p++) {
                unsigned long long a = add2(pw2[p], B1.y);
                a = fma2(A1.x, px2[p], a);
                a = fma2(A1.y, py2[p], a);
                a = fma2(B1.x, pz2[p], a);
                float lo, hi;
                unpack2(lo, hi, a);
                mp[2 * p]     = fminf(mp[2 * p], lo);
                mp[2 * p + 1] = fminf(mp[2 * p + 1], hi);
                tm[p] = fminf(lo, hi);
            }
            m1 = fminf(fminf(tm[0], tm[1]), fminf(tm[2], tm[3]));
        }
        unsigned u0 = redux_min_u32(f2o(m0));
        unsigned u1 = redux_min_u32(f2o(m1));
        if (lane == 0) {
            shminw[warp][j]     = u0;
            shminw[warp][j + 1] = u1;
        }
    }
    __syncthreads();

    // gt-direction publish: combine warps (integer min), decode, plain store.
    float* gm = g_ming_part[pb] + (long)b * NN + (long)gs * CHUNK_G;
    for (int j = tid; j < CHUNK_G; j += THREADS) {
        unsigned v = shminw[0][j];
#pragma unroll
        for (int w = 1; w < NWARP; w++) v = min(v, shminw[w][j]);
        gm[j] = o2f(v);
    }

    // pred-direction publish: plain store to this gs's slice.
    float* pm = g_minp_part[gs] + (long)b * NN + (long)pb * TILE_P;
#pragma unroll
    for (int r = 0; r < RR; r++)
        pm[r * THREADS + tid] = mp[r];
}

#define F1BLOCKS 128
#define F1T 256
#define PTS_PER_BLK (BB * NN / F1BLOCKS)   // 512

__global__ __launch_bounds__(F1T)
void chamfer_finalize1() {
    __shared__ double sh[F1T];
    const int base = blockIdx.x * PTS_PER_BLK;
    double acc = 0.0;
    for (int i = threadIdx.x; i < PTS_PER_BLK; i += F1T) {
        int idx = base + i;
        float vp = g_minp_part[0][idx];
#pragma unroll
        for (int s = 1; s < SPLIT_G; s++) vp = fminf(vp, g_minp_part[s][idx]);
        float vg = g_ming_part[0][idx];
#pragma unroll
        for (int s = 1; s < PBLK; s++) vg = fminf(vg, g_ming_part[s][idx]);
        acc += (double)vp + (double)vg;
    }
    sh[threadIdx.x] = acc;
    __syncthreads();
    for (int s = F1T / 2; s > 0; s >>= 1) {
        if (threadIdx.x < s) sh[threadIdx.x] += sh[threadIdx.x + s];
        __syncthreads();
    }
    if (threadIdx.x == 0) g_partial[blockIdx.x] = sh[0];
}

__global__ void chamfer_finalize2(float* __restrict__ out) {
    __shared__ double sh[F1BLOCKS];
    sh[threadIdx.x] = g_partial[threadIdx.x];
    __syncthreads();
    for (int s = F1BLOCKS / 2; s > 0; s >>= 1) {
        if (threadIdx.x < s) sh[threadIdx.x] += sh[threadIdx.x + s];
        __syncthreads();
    }
    if (threadIdx.x == 0)
        out[0] = (float)(sh[0] / ((double)NN * (double)BB));
}

extern "C" void kernel_launch(void* const* d_in, const int* in_sizes, int n_in,
                              void* d_out, int out_size) {
    const float* pred = (const float*)d_in[0];
    const float* gt   = (const float*)d_in[1];
    float* out = (float*)d_out;

    dim3 grid(BB * PBLK, SPLIT_G);
    chamfer_main<<<grid, THREADS>>>(pred, gt);
    chamfer_finalize1<<<F1BLOCKS, F1T>>>();
    chamfer_finalize2<<<1, F1BLOCKS>>>(out);
}